// round 13
// baseline (speedup 1.0000x reference)
#include <cuda_runtime.h>

// DynamicMaskHead fused kernel for GB300 (sm_103a), round 13.
// Law from R9/R11/R12: weight-LDS amortization (4px) only pays at 24 warps/SM.
// R13 = 4px body engineered for the 85-reg cap at NT=192 @ 4 CTA (R11 launch
// config, grid (200,6), 16-row slabs, 2-wave fill):
//  - bias fused into input-0 FFMA2 (no acc-init movs)
//  - features JIT per 2-channel group (LDG.128, consumed immediately)
//  - layer 1 in two pixel-halves (reload weights; halves peak pressure)
//  - l2b hoisted; logits stored as 2x STS.128
// LSU per 4px ~141 vs 2x95=190 in R11 (-26%) at identical warps/fill.

#define WW   160
#define OW   320
#define HW   15360
#define NP   169
#define NT   192

// weight-pair layout (u64 indices in swp):
//   [0,80)    l0wT: input-major, i*8 + c
//   [80,88)   l0b
//   [88,168)  l1 blocks: c*10 + {0..7: w, 8: bias, 9: w2(pre-scaled 0.5)}
//   [168]     l2b (pre-scaled 0.5)
#define SWPAIRS 169
#define TILE_PAIRS (17 * WW)
#define SMEM_BYTES ((TILE_PAIRS + SWPAIRS + 1) * 8)

typedef unsigned long long u64;

__device__ __forceinline__ u64 pk(float lo, float hi) {
    u64 r; asm("mov.b64 %0, {%1, %2};" : "=l"(r) : "f"(lo), "f"(hi)); return r;
}
__device__ __forceinline__ u64 dup(float v) {
    u64 r; asm("mov.b64 %0, {%1, %1};" : "=l"(r) : "f"(v)); return r;
}
__device__ __forceinline__ void upk(u64 v, float& lo, float& hi) {
    asm("mov.b64 {%0, %1}, %2;" : "=f"(lo), "=f"(hi) : "l"(v));
}
__device__ __forceinline__ u64 ffma2(u64 a, u64 b, u64 c) {
    u64 d; asm("fma.rn.f32x2 %0, %1, %2, %3;" : "=l"(d) : "l"(a), "l"(b), "l"(c)); return d;
}
__device__ __forceinline__ u64 add2(u64 a, u64 b) {
    u64 d; asm("add.rn.f32x2 %0, %1, %2;" : "=l"(d) : "l"(a), "l"(b)); return d;
}
__device__ __forceinline__ u64 mul2(u64 a, u64 b) {
    u64 d; asm("mul.rn.f32x2 %0, %1, %2;" : "=l"(d) : "l"(a), "l"(b)); return d;
}
__device__ __forceinline__ u64 relu2(u64 v) {
    float lo, hi; upk(v, lo, hi);
    return pk(fmaxf(lo, 0.0f), fmaxf(hi, 0.0f));
}
// x = 0.5*logit: sigmoid(L) = 0.5*tanh(0.5L) + 0.5
__device__ __forceinline__ float sig_h(float x) {
    float t;
    asm("tanh.approx.f32 %0, %1;" : "=f"(t) : "f"(x));
    return fmaf(0.5f, t, 0.5f);
}

__global__ __launch_bounds__(NT, 4)
void dmh_kernel(const float* __restrict__ feats,     // [2, 8, 96, 160]
                const float* __restrict__ p1,        // [N, 169]
                const float* __restrict__ p2,        // [N, 169]
                const float* __restrict__ loc,       // [N, 2]
                const float* __restrict__ off,       // [N, 2]
                const int*   __restrict__ imi,       // [N]
                const int*   __restrict__ fpn,       // [N]
                float*       __restrict__ out)       // [2, N, 192, 320]
{
    extern __shared__ u64 smem_u64[];
    u64* sLp = smem_u64;                       // [TILE_PAIRS] packed half-logits
    u64* swp = smem_u64 + TILE_PAIRS;          // [SWPAIRS] weight pairs

    const int tid    = threadIdx.x;
    const int inst   = blockIdx.x;
    const int slab   = blockIdx.y;             // 0..5
    const int n_inst = gridDim.x;

    // ---- Repack: interleave head0/head1 weights into pairs ----
    if (tid < NP) {
        float w1 = p1[inst * NP + tid];
        float w2 = p2[inst * NP + tid];
        int d;
        if      (tid < 80)  { const int c = tid / 10; d = (tid - c * 10) * 8 + c; }        // l0wT
        else if (tid < 144) { const int i = tid - 80; d = 88 + (i / 8) * 10 + (i % 8); }   // l1w
        else if (tid < 152) { d = 88 + (tid - 144) * 10 + 9; w1 *= 0.5f; w2 *= 0.5f; }     // l2w
        else if (tid < 160) { d = 80 + (tid - 152); }                                      // l0b
        else if (tid < 168) { d = 88 + (tid - 160) * 10 + 8; }                             // l1b
        else                { d = 168; w1 *= 0.5f; w2 *= 0.5f; }                           // l2b
        swp[d] = pk(w1, w2);
    }

    const int   lvl     = fpn[inst];
    const float inv_soi = 1.0f / (64.0f * (float)(1 << lvl));
    const float lx0 = loc[2 * inst + 0];
    const float ly0 = loc[2 * inst + 1];
    const float lx1 = lx0 + off[2 * inst + 0] * 128.0f;
    const float ly1 = ly0 + off[2 * inst + 1] * 128.0f;
    const float* fb = feats + (size_t)imi[inst] * (8 * HW);
    const float dxs = -8.0f * inv_soi;
    __syncthreads();

    const u64 l2b = swp[168];                  // hoisted (loop-invariant)

    // ---------------- Phase 1: packed MLP, 4 px x 2 heads per iter ----------
    // slab s -> output rows [32s, 32s+32) -> input rows [16s-(s>0), 16s+16)
    const int ybase = 16 * slab - (slab ? 1 : 0);
    const int nrows = 16 + (slab ? 1 : 0);     // 16 or 17
    const int ng    = nrows * (WW / 4);

    #pragma unroll 1
    for (int g = tid; g < ng; g += NT) {
        const int rowl = g / (WW / 4);
        const int px   = (g - rowl * (WW / 4)) * 4;
        const int y    = ybase + rowl;
        const int base = y * WW + px;

        u64 a[4][8];

        // ---- input 0 (x-coord, per-pixel) fused with bias init ----
        {
            const float yc = (float)(y * 8 + 4);
            const float xc = (float)(px * 8 + 4);
            const u64 dd  = dup(dxs);
            u64 xp[4];
            xp[0] = pk((lx0 - xc) * inv_soi, (lx1 - xc) * inv_soi);
            xp[1] = add2(xp[0], dd);
            xp[2] = add2(xp[1], dd);
            xp[3] = add2(xp[2], dd);

            const ulonglong2* Bp = reinterpret_cast<const ulonglong2*>(swp + 80);
            const ulonglong2 b0 = Bp[0], b1 = Bp[1], b2 = Bp[2], b3 = Bp[3];
            const ulonglong2* Wp = reinterpret_cast<const ulonglong2*>(swp);
            const ulonglong2 wa = Wp[0], wb = Wp[1], wc = Wp[2], wd = Wp[3];
            #pragma unroll
            for (int k = 0; k < 4; ++k) {
                a[k][0] = ffma2(xp[k], wa.x, b0.x);
                a[k][1] = ffma2(xp[k], wa.y, b0.y);
                a[k][2] = ffma2(xp[k], wb.x, b1.x);
                a[k][3] = ffma2(xp[k], wb.y, b1.y);
                a[k][4] = ffma2(xp[k], wc.x, b2.x);
                a[k][5] = ffma2(xp[k], wc.y, b2.y);
                a[k][6] = ffma2(xp[k], wd.x, b3.x);
                a[k][7] = ffma2(xp[k], wd.y, b3.y);
            }

            // ---- input 1 (y-coord, same for all 4 px) ----
            const u64 yv = pk((ly0 - yc) * inv_soi, (ly1 - yc) * inv_soi);
            const ulonglong2* Wq = reinterpret_cast<const ulonglong2*>(swp + 8);
            const ulonglong2 va = Wq[0], vb = Wq[1], vc = Wq[2], vd = Wq[3];
            #pragma unroll
            for (int k = 0; k < 4; ++k) {
                a[k][0] = ffma2(yv, va.x, a[k][0]);
                a[k][1] = ffma2(yv, va.y, a[k][1]);
                a[k][2] = ffma2(yv, vb.x, a[k][2]);
                a[k][3] = ffma2(yv, vb.y, a[k][3]);
                a[k][4] = ffma2(yv, vc.x, a[k][4]);
                a[k][5] = ffma2(yv, vc.y, a[k][5]);
                a[k][6] = ffma2(yv, vd.x, a[k][6]);
                a[k][7] = ffma2(yv, vd.y, a[k][7]);
            }
        }

        // ---- features: 4 groups of 2 channels, consumed immediately ----
        #pragma unroll
        for (int grp = 0; grp < 4; ++grp) {
            const float4 fA = *reinterpret_cast<const float4*>(fb + (2 * grp)     * HW + base);
            const float4 fB = *reinterpret_cast<const float4*>(fb + (2 * grp + 1) * HW + base);
            #pragma unroll
            for (int j = 0; j < 2; ++j) {
                const float4 F = j ? fB : fA;
                const ulonglong2* Wp =
                    reinterpret_cast<const ulonglong2*>(swp + (2 + 2 * grp + j) * 8);
                const ulonglong2 wa = Wp[0], wb = Wp[1], wc = Wp[2], wd = Wp[3];
                #pragma unroll
                for (int k = 0; k < 4; ++k) {
                    const u64 d = dup(k == 0 ? F.x : (k == 1 ? F.y : (k == 2 ? F.z : F.w)));
                    a[k][0] = ffma2(d, wa.x, a[k][0]);
                    a[k][1] = ffma2(d, wa.y, a[k][1]);
                    a[k][2] = ffma2(d, wb.x, a[k][2]);
                    a[k][3] = ffma2(d, wb.y, a[k][3]);
                    a[k][4] = ffma2(d, wc.x, a[k][4]);
                    a[k][5] = ffma2(d, wc.y, a[k][5]);
                    a[k][6] = ffma2(d, wd.x, a[k][6]);
                    a[k][7] = ffma2(d, wd.y, a[k][7]);
                }
            }
        }

        // ---- ReLU ----
        #pragma unroll
        for (int k = 0; k < 4; ++k)
            #pragma unroll
            for (int c = 0; c < 8; ++c)
                a[k][c] = relu2(a[k][c]);

        // ---- layer 1 + layer 2, in two pixel-halves (weights reloaded) ----
        u64 oo[4];
        #pragma unroll
        for (int half = 0; half < 2; ++half) {
            const int kA = 2 * half, kB = 2 * half + 1;
            u64 oA = l2b, oB = l2b;
            #pragma unroll
            for (int c = 0; c < 8; ++c) {
                const ulonglong2* Wp =
                    reinterpret_cast<const ulonglong2*>(swp + 88 + c * 10);
                const ulonglong2 wa = Wp[0], wb = Wp[1], wc = Wp[2], wd = Wp[3];
                const ulonglong2 bw = Wp[4];      // {bias, w2}
                u64 tA = ffma2(a[kA][0], wa.x, bw.x);
                u64 tB = ffma2(a[kB][0], wa.x, bw.x);
                tA = ffma2(a[kA][1], wa.y, tA);  tB = ffma2(a[kB][1], wa.y, tB);
                tA = ffma2(a[kA][2], wb.x, tA);  tB = ffma2(a[kB][2], wb.x, tB);
                tA = ffma2(a[kA][3], wb.y, tA);  tB = ffma2(a[kB][3], wb.y, tB);
                tA = ffma2(a[kA][4], wc.x, tA);  tB = ffma2(a[kB][4], wc.x, tB);
                tA = ffma2(a[kA][5], wc.y, tA);  tB = ffma2(a[kB][5], wc.y, tB);
                tA = ffma2(a[kA][6], wd.x, tA);  tB = ffma2(a[kB][6], wd.x, tB);
                tA = ffma2(a[kA][7], wd.y, tA);  tB = ffma2(a[kB][7], wd.y, tB);
                oA = ffma2(relu2(tA), bw.y, oA);
                oB = ffma2(relu2(tB), bw.y, oB);
            }
            oo[kA] = oA; oo[kB] = oB;
        }

        // ---- store packed half-logits: 2x STS.128 (px % 4 == 0) ----
        u64* dst = sLp + rowl * WW + px;
        *reinterpret_cast<ulonglong2*>(dst)     = make_ulonglong2(oo[0], oo[1]);
        *reinterpret_cast<ulonglong2*>(dst + 2) = make_ulonglong2(oo[2], oo[3]);
    }
    __syncthreads();

    // ---------------- Phase 2: packed bilinear x2 + sigmoid (R11 verbatim) ---
    const u64 H = dup(0.5f);
    const u64 Q = dup(0.25f);
    float* ob0 = out + (size_t)inst * (192 * OW);
    float* ob1 = out + ((size_t)n_inst + inst) * (192 * OW);

    #pragma unroll 1
    for (int it = 0; it < 14; ++it) {
        const int q = tid + it * NT;
        if (q >= 32 * 80) break;
        const int oyl = q / 80;                 // 0..31
        const int g   = q - oyl * 80;           // 0..79
        const int oy  = 32 * slab + oyl;

        const int r1  = oy >> 1;
        const int rA  = (oy & 1) ? r1 : ((r1 > 0) ? r1 - 1 : 0);
        const u64* RB = sLp + (r1 - ybase) * WW;
        const u64* RA = sLp + (rA - ybase) * WW;

        const int c0  = 2 * g;                  // even -> 16B aligned
        const int cm1 = (g > 0) ? c0 - 1 : c0;

        const ulonglong2 pb = *reinterpret_cast<const ulonglong2*>(RB + c0);
        const ulonglong2 pa = *reinterpret_cast<const ulonglong2*>(RA + c0);
        const u64 Sm = add2(RA[cm1], RB[cm1]);
        const u64 S0 = add2(pa.x, pb.x);
        const u64 S1 = add2(pa.y, pb.y);

        const u64 e0 = mul2(add2(Sm, S0), Q);
        const u64 e1 = mul2(S0, H);
        const u64 e2 = mul2(add2(S0, S1), Q);
        const u64 e3 = mul2(S1, H);

        float a0, b0, a1, b1, a2, b2, a3, b3;
        upk(e0, a0, b0); upk(e1, a1, b1); upk(e2, a2, b2); upk(e3, a3, b3);

        float4 v0, v1;
        v0.x = sig_h(a0); v0.y = sig_h(a1); v0.z = sig_h(a2); v0.w = sig_h(a3);
        v1.x = sig_h(b0); v1.y = sig_h(b1); v1.z = sig_h(b2); v1.w = sig_h(b3);

        const int o = oy * OW + 4 * g;
        *reinterpret_cast<float4*>(ob0 + o) = v0;
        *reinterpret_cast<float4*>(ob1 + o) = v1;
    }
}

extern "C" void kernel_launch(void* const* d_in, const int* in_sizes, int n_in,
                              void* d_out, int out_size)
{
    const float* feats = (const float*)d_in[0];
    const float* p1    = (const float*)d_in[1];
    const float* p2    = (const float*)d_in[2];
    const float* loc   = (const float*)d_in[3];
    const float* off   = (const float*)d_in[4];
    const int*   imi   = (const int*)  d_in[5];
    const int*   fpn   = (const int*)  d_in[6];
    float* out = (float*)d_out;

    const int n_inst = in_sizes[5];   // 200

    static bool attr_set = false;
    if (!attr_set) {
        cudaFuncSetAttribute(dmh_kernel,
                             cudaFuncAttributeMaxDynamicSharedMemorySize,
                             (int)SMEM_BYTES);
        attr_set = true;
    }

    dim3 grid(n_inst, 6);             // 1200 blocks ~ 2 waves @ 4 CTA/SM, 24 warps
    dmh_kernel<<<grid, NT, SMEM_BYTES>>>(feats, p1, p2, loc, off, imi, fpn, out);
}

// round 14
// speedup vs baseline: 7.0291x; 7.0291x over previous
#include <cuda_runtime.h>

// DynamicMaskHead fused kernel for GB300 (sm_103a), round 14.
// = Round 11 (53.7us best: heads packed f32x2, 2px/iter, NT=192 @ 4 CTA/SM,
// 16-row slabs, grid (200,6)) with three zero-structure instruction removals:
//  - l0 bias fused into input-0 FFMA2 (kills 16 init MOVs; same LDS count)
//  - dup(dxs) hoisted out of the phase-1 loop
//  - l2b (swp[168]) hoisted out of the phase-1 loop
// R13's 4px attempt spilled catastrophically (needs ~96 regs vs 85 cap);
// weight-amortization axis is closed: 2px @ 24 warps/SM is the Pareto point.

#define WW   160
#define OW   320
#define HW   15360
#define NP   169
#define NT   192

// weight-pair layout (u64 indices in swp):
//   [0,80)    l0wT: input-major, i*8 + c
//   [80,88)   l0b
//   [88,168)  l1 blocks: c*10 + {0..7: w, 8: bias, 9: w2(pre-scaled 0.5)}
//   [168]     l2b (pre-scaled 0.5)
#define SWPAIRS 169
#define TILE_PAIRS (17 * WW)                 // 17 rows max per slab
#define SMEM_BYTES ((TILE_PAIRS + SWPAIRS + 1) * 8)

typedef unsigned long long u64;

__device__ __forceinline__ u64 pk(float lo, float hi) {
    u64 r; asm("mov.b64 %0, {%1, %2};" : "=l"(r) : "f"(lo), "f"(hi)); return r;
}
__device__ __forceinline__ u64 dup(float v) {
    u64 r; asm("mov.b64 %0, {%1, %1};" : "=l"(r) : "f"(v)); return r;
}
__device__ __forceinline__ void upk(u64 v, float& lo, float& hi) {
    asm("mov.b64 {%0, %1}, %2;" : "=f"(lo), "=f"(hi) : "l"(v));
}
__device__ __forceinline__ u64 ffma2(u64 a, u64 b, u64 c) {
    u64 d; asm("fma.rn.f32x2 %0, %1, %2, %3;" : "=l"(d) : "l"(a), "l"(b), "l"(c)); return d;
}
__device__ __forceinline__ u64 add2(u64 a, u64 b) {
    u64 d; asm("add.rn.f32x2 %0, %1, %2;" : "=l"(d) : "l"(a), "l"(b)); return d;
}
__device__ __forceinline__ u64 mul2(u64 a, u64 b) {
    u64 d; asm("mul.rn.f32x2 %0, %1, %2;" : "=l"(d) : "l"(a), "l"(b)); return d;
}
__device__ __forceinline__ u64 relu2(u64 v) {
    float lo, hi; upk(v, lo, hi);
    return pk(fmaxf(lo, 0.0f), fmaxf(hi, 0.0f));
}
// x = 0.5*logit: sigmoid(L) = 0.5*tanh(0.5L) + 0.5
__device__ __forceinline__ float sig_h(float x) {
    float t;
    asm("tanh.approx.f32 %0, %1;" : "=f"(t) : "f"(x));
    return fmaf(0.5f, t, 0.5f);
}

__global__ __launch_bounds__(NT, 4)
void dmh_kernel(const float* __restrict__ feats,     // [2, 8, 96, 160]
                const float* __restrict__ p1,        // [N, 169]
                const float* __restrict__ p2,        // [N, 169]
                const float* __restrict__ loc,       // [N, 2]
                const float* __restrict__ off,       // [N, 2]
                const int*   __restrict__ imi,       // [N]
                const int*   __restrict__ fpn,       // [N]
                float*       __restrict__ out)       // [2, N, 192, 320]
{
    extern __shared__ u64 smem_u64[];
    u64* sLp = smem_u64;                       // [TILE_PAIRS] packed half-logits
    u64* swp = smem_u64 + TILE_PAIRS;          // [SWPAIRS] weight pairs

    const int tid    = threadIdx.x;
    const int inst   = blockIdx.x;
    const int slab   = blockIdx.y;             // 0..5
    const int n_inst = gridDim.x;

    // ---- Repack: interleave head0/head1 weights into pairs ----
    if (tid < NP) {
        float w1 = p1[inst * NP + tid];
        float w2 = p2[inst * NP + tid];
        int d;
        if      (tid < 80)  { const int c = tid / 10; d = (tid - c * 10) * 8 + c; }        // l0wT
        else if (tid < 144) { const int i = tid - 80; d = 88 + (i / 8) * 10 + (i % 8); }   // l1w
        else if (tid < 152) { d = 88 + (tid - 144) * 10 + 9; w1 *= 0.5f; w2 *= 0.5f; }     // l2w
        else if (tid < 160) { d = 80 + (tid - 152); }                                      // l0b
        else if (tid < 168) { d = 88 + (tid - 160) * 10 + 8; }                             // l1b
        else                { d = 168; w1 *= 0.5f; w2 *= 0.5f; }                           // l2b
        swp[d] = pk(w1, w2);
    }

    const int   lvl     = fpn[inst];
    const float inv_soi = 1.0f / (64.0f * (float)(1 << lvl));
    const float lx0 = loc[2 * inst + 0];
    const float ly0 = loc[2 * inst + 1];
    const float lx1 = lx0 + off[2 * inst + 0] * 128.0f;
    const float ly1 = ly0 + off[2 * inst + 1] * 128.0f;
    const float* fb = feats + (size_t)imi[inst] * (8 * HW);
    const float dxs = -8.0f * inv_soi;
    __syncthreads();

    // loop-invariant hoists
    const u64 dd  = dup(dxs);
    const u64 l2b = swp[168];

    // ---------------- Phase 1: packed MLP, 2 px x 2 heads per iter ----------
    // slab s -> output rows [32s, 32s+32) -> input rows [16s-(s>0), 16s+16)
    const int ybase = 16 * slab - (slab ? 1 : 0);
    const int nrows = 16 + (slab ? 1 : 0);     // 16 or 17
    const int npx   = nrows * WW;

    #pragma unroll 1
    for (int p = 2 * tid; p < npx; p += 2 * NT) {
        const int rowl = p / WW;
        const int px   = p - rowl * WW;          // even
        const int y    = ybase + rowl;
        const int base = y * WW + px;

        // coordinate pairs {head0, head1}
        const float yc = (float)(y * 8 + 4);
        const float xc = (float)(px * 8 + 4);
        const u64 yp  = pk((ly0 - yc) * inv_soi, (ly1 - yc) * inv_soi);
        const u64 xpA = pk((lx0 - xc) * inv_soi, (lx1 - xc) * inv_soi);
        const u64 xpB = add2(xpA, dd);

        // features for the 2 pixels (8 x LDG.64)
        float2 f2[8];
        #pragma unroll
        for (int j = 0; j < 8; ++j)
            f2[j] = *reinterpret_cast<const float2*>(fb + j * HW + base);

        // layer 0, input 0 (x-coord): bias fused into the FFMA2 c-operand
        u64 a0[8], a1[8];
        {
            const ulonglong2* Bp = reinterpret_cast<const ulonglong2*>(swp + 80);
            const ulonglong2 b0 = Bp[0], b1 = Bp[1], b2 = Bp[2], b3 = Bp[3];
            const ulonglong2* Wp = reinterpret_cast<const ulonglong2*>(swp);
            const ulonglong2 wa = Wp[0], wb = Wp[1], wc = Wp[2], wd = Wp[3];
            a0[0] = ffma2(xpA, wa.x, b0.x);  a1[0] = ffma2(xpB, wa.x, b0.x);
            a0[1] = ffma2(xpA, wa.y, b0.y);  a1[1] = ffma2(xpB, wa.y, b0.y);
            a0[2] = ffma2(xpA, wb.x, b1.x);  a1[2] = ffma2(xpB, wb.x, b1.x);
            a0[3] = ffma2(xpA, wb.y, b1.y);  a1[3] = ffma2(xpB, wb.y, b1.y);
            a0[4] = ffma2(xpA, wc.x, b2.x);  a1[4] = ffma2(xpB, wc.x, b2.x);
            a0[5] = ffma2(xpA, wc.y, b2.y);  a1[5] = ffma2(xpB, wc.y, b2.y);
            a0[6] = ffma2(xpA, wd.x, b3.x);  a1[6] = ffma2(xpB, wd.x, b3.x);
            a0[7] = ffma2(xpA, wd.y, b3.y);  a1[7] = ffma2(xpB, wd.y, b3.y);
        }

        // layer 0, remaining inputs (y-coord + 8 features)
        #define L0STEP(I, XA, XB)                                             \
        {                                                                     \
            const ulonglong2* Wp = reinterpret_cast<const ulonglong2*>(swp + (I) * 8); \
            const ulonglong2 wa = Wp[0], wb = Wp[1], wc = Wp[2], wd = Wp[3];  \
            a0[0] = ffma2(XA, wa.x, a0[0]);  a1[0] = ffma2(XB, wa.x, a1[0]);  \
            a0[1] = ffma2(XA, wa.y, a0[1]);  a1[1] = ffma2(XB, wa.y, a1[1]);  \
            a0[2] = ffma2(XA, wb.x, a0[2]);  a1[2] = ffma2(XB, wb.x, a1[2]);  \
            a0[3] = ffma2(XA, wb.y, a0[3]);  a1[3] = ffma2(XB, wb.y, a1[3]);  \
            a0[4] = ffma2(XA, wc.x, a0[4]);  a1[4] = ffma2(XB, wc.x, a1[4]);  \
            a0[5] = ffma2(XA, wc.y, a0[5]);  a1[5] = ffma2(XB, wc.y, a1[5]);  \
            a0[6] = ffma2(XA, wd.x, a0[6]);  a1[6] = ffma2(XB, wd.x, a1[6]);  \
            a0[7] = ffma2(XA, wd.y, a0[7]);  a1[7] = ffma2(XB, wd.y, a1[7]);  \
        }
        L0STEP(1, yp, yp)
        #pragma unroll
        for (int j = 0; j < 8; ++j) {
            const u64 fd0 = dup(f2[j].x);
            const u64 fd1 = dup(f2[j].y);
            L0STEP(2 + j, fd0, fd1)
        }
        #undef L0STEP

        #pragma unroll
        for (int c = 0; c < 8; ++c) { a0[c] = relu2(a0[c]); a1[c] = relu2(a1[c]); }

        // layer 1 channel-outer ({bias,w2} packed), layer 2 streamed into o
        u64 o0 = l2b, o1 = l2b;
        #pragma unroll
        for (int c = 0; c < 8; ++c) {
            const ulonglong2* Wp = reinterpret_cast<const ulonglong2*>(swp + 88 + c * 10);
            const ulonglong2 wa = Wp[0], wb = Wp[1], wc = Wp[2], wd = Wp[3];
            const ulonglong2 bw = Wp[4];          // {bias, w2}
            u64 b0 = ffma2(a0[0], wa.x, bw.x);
            u64 b1 = ffma2(a1[0], wa.x, bw.x);
            b0 = ffma2(a0[1], wa.y, b0);  b1 = ffma2(a1[1], wa.y, b1);
            b0 = ffma2(a0[2], wb.x, b0);  b1 = ffma2(a1[2], wb.x, b1);
            b0 = ffma2(a0[3], wb.y, b0);  b1 = ffma2(a1[3], wb.y, b1);
            b0 = ffma2(a0[4], wc.x, b0);  b1 = ffma2(a1[4], wc.x, b1);
            b0 = ffma2(a0[5], wc.y, b0);  b1 = ffma2(a1[5], wc.y, b1);
            b0 = ffma2(a0[6], wd.x, b0);  b1 = ffma2(a1[6], wd.x, b1);
            b0 = ffma2(a0[7], wd.y, b0);  b1 = ffma2(a1[7], wd.y, b1);
            o0 = ffma2(relu2(b0), bw.y, o0);
            o1 = ffma2(relu2(b1), bw.y, o1);
        }

        sLp[rowl * WW + px]     = o0;    // packed {h0, h1} half-logits
        sLp[rowl * WW + px + 1] = o1;
    }
    __syncthreads();

    // ---------------- Phase 2: packed bilinear x2 + sigmoid ------------------
    // S_i = P[rA][i] + P[rB][i]  (rA==rB for odd rows -> S = 2P)
    //   col 4g: 0.25*(S_{cm1}+S_{c0})   4g+1: 0.5*S_{c0}
    //   4g+2:   0.25*(S_{c0}+S_{c1})    4g+3: 0.5*S_{c1}
    const u64 H = dup(0.5f);
    const u64 Q = dup(0.25f);
    float* ob0 = out + (size_t)inst * (192 * OW);
    float* ob1 = out + ((size_t)n_inst + inst) * (192 * OW);

    // 32 output rows x 80 quad-groups = 2560 items; 14 guarded iters
    #pragma unroll 1
    for (int it = 0; it < 14; ++it) {
        const int q = tid + it * NT;
        if (q >= 32 * 80) break;
        const int oyl = q / 80;                 // 0..31
        const int g   = q - oyl * 80;           // 0..79
        const int oy  = 32 * slab + oyl;

        const int r1  = oy >> 1;
        const int rA  = (oy & 1) ? r1 : ((r1 > 0) ? r1 - 1 : 0);
        const u64* RB = sLp + (r1 - ybase) * WW;
        const u64* RA = sLp + (rA - ybase) * WW;

        const int c0  = 2 * g;                  // even -> 16B aligned
        const int cm1 = (g > 0) ? c0 - 1 : c0;

        const ulonglong2 pb = *reinterpret_cast<const ulonglong2*>(RB + c0);
        const ulonglong2 pa = *reinterpret_cast<const ulonglong2*>(RA + c0);
        const u64 Sm = add2(RA[cm1], RB[cm1]);
        const u64 S0 = add2(pa.x, pb.x);
        const u64 S1 = add2(pa.y, pb.y);

        const u64 e0 = mul2(add2(Sm, S0), Q);
        const u64 e1 = mul2(S0, H);
        const u64 e2 = mul2(add2(S0, S1), Q);
        const u64 e3 = mul2(S1, H);

        float a0, b0, a1, b1, a2, b2, a3, b3;
        upk(e0, a0, b0); upk(e1, a1, b1); upk(e2, a2, b2); upk(e3, a3, b3);

        float4 v0, v1;
        v0.x = sig_h(a0); v0.y = sig_h(a1); v0.z = sig_h(a2); v0.w = sig_h(a3);
        v1.x = sig_h(b0); v1.y = sig_h(b1); v1.z = sig_h(b2); v1.w = sig_h(b3);

        const int o = oy * OW + 4 * g;
        *reinterpret_cast<float4*>(ob0 + o) = v0;
        *reinterpret_cast<float4*>(ob1 + o) = v1;
    }
}

extern "C" void kernel_launch(void* const* d_in, const int* in_sizes, int n_in,
                              void* d_out, int out_size)
{
    const float* feats = (const float*)d_in[0];
    const float* p1    = (const float*)d_in[1];
    const float* p2    = (const float*)d_in[2];
    const float* loc   = (const float*)d_in[3];
    const float* off   = (const float*)d_in[4];
    const int*   imi   = (const int*)  d_in[5];
    const int*   fpn   = (const int*)  d_in[6];
    float* out = (float*)d_out;

    const int n_inst = in_sizes[5];   // 200

    static bool attr_set = false;
    if (!attr_set) {
        cudaFuncSetAttribute(dmh_kernel,
                             cudaFuncAttributeMaxDynamicSharedMemorySize,
                             (int)SMEM_BYTES);
        attr_set = true;
    }

    dim3 grid(n_inst, 6);             // 1200 blocks ~ 2 waves @ 4 CTA/SM, 24 warps
    dmh_kernel<<<grid, NT, SMEM_BYTES>>>(feats, p1, p2, loc, off, imi, fpn, out);
}

// round 15
// speedup vs baseline: 7.2104x; 1.0258x over previous
#include <cuda_runtime.h>

// DynamicMaskHead fused kernel for GB300 (sm_103a) — FINAL (= round 11, 53.7us).
// Design (each element bench-validated):
//  - heads packed into f32x2 lanes: weights interleaved {h0,h1} in smem,
//    fma.rn.f32x2 computes both heads' MLPs at once (R8: -12% vs scalar)
//  - 2 px/thread, NT=192 @ 4 CTA/SM = 24 warps/SM (R9/R12/R13: any wider
//    pixel tile spills past the 85-reg cap or drops warps -> net loss)
//  - 16-row slabs, grid (200,6) = 1200 blocks ~ 2 waves (R10/R11: wave fill)
//  - layer-1 {bias,w2} packed -> LDS.128; layer-2 pre-scaled 0.5 so smem
//    holds half-logits and the x2 bilinear + sigmoid needs no extra muls
//  - phase 2 fully packed (add/mul.f32x2), tanh.approx sigmoid, STG.128/head

#define WW   160
#define OW   320
#define HW   15360
#define NP   169
#define NT   192

// weight-pair layout (u64 indices in swp):
//   [0,80)    l0wT: input-major, i*8 + c
//   [80,88)   l0b
//   [88,168)  l1 blocks: c*10 + {0..7: w, 8: bias, 9: w2(pre-scaled 0.5)}
//   [168]     l2b (pre-scaled 0.5)
#define SWPAIRS 169
#define TILE_PAIRS (17 * WW)                 // 17 rows max per slab
#define SMEM_BYTES ((TILE_PAIRS + SWPAIRS + 1) * 8)

typedef unsigned long long u64;

__device__ __forceinline__ u64 pk(float lo, float hi) {
    u64 r; asm("mov.b64 %0, {%1, %2};" : "=l"(r) : "f"(lo), "f"(hi)); return r;
}
__device__ __forceinline__ u64 dup(float v) {
    u64 r; asm("mov.b64 %0, {%1, %1};" : "=l"(r) : "f"(v)); return r;
}
__device__ __forceinline__ void upk(u64 v, float& lo, float& hi) {
    asm("mov.b64 {%0, %1}, %2;" : "=f"(lo), "=f"(hi) : "l"(v));
}
__device__ __forceinline__ u64 ffma2(u64 a, u64 b, u64 c) {
    u64 d; asm("fma.rn.f32x2 %0, %1, %2, %3;" : "=l"(d) : "l"(a), "l"(b), "l"(c)); return d;
}
__device__ __forceinline__ u64 add2(u64 a, u64 b) {
    u64 d; asm("add.rn.f32x2 %0, %1, %2;" : "=l"(d) : "l"(a), "l"(b)); return d;
}
__device__ __forceinline__ u64 mul2(u64 a, u64 b) {
    u64 d; asm("mul.rn.f32x2 %0, %1, %2;" : "=l"(d) : "l"(a), "l"(b)); return d;
}
__device__ __forceinline__ u64 relu2(u64 v) {
    float lo, hi; upk(v, lo, hi);
    return pk(fmaxf(lo, 0.0f), fmaxf(hi, 0.0f));
}
// x = 0.5*logit: sigmoid(L) = 0.5*tanh(0.5L) + 0.5
__device__ __forceinline__ float sig_h(float x) {
    float t;
    asm("tanh.approx.f32 %0, %1;" : "=f"(t) : "f"(x));
    return fmaf(0.5f, t, 0.5f);
}

__global__ __launch_bounds__(NT, 4)
void dmh_kernel(const float* __restrict__ feats,     // [2, 8, 96, 160]
                const float* __restrict__ p1,        // [N, 169]
                const float* __restrict__ p2,        // [N, 169]
                const float* __restrict__ loc,       // [N, 2]
                const float* __restrict__ off,       // [N, 2]
                const int*   __restrict__ imi,       // [N]
                const int*   __restrict__ fpn,       // [N]
                float*       __restrict__ out)       // [2, N, 192, 320]
{
    extern __shared__ u64 smem_u64[];
    u64* sLp = smem_u64;                       // [TILE_PAIRS] packed half-logits
    u64* swp = smem_u64 + TILE_PAIRS;          // [SWPAIRS] weight pairs

    const int tid    = threadIdx.x;
    const int inst   = blockIdx.x;
    const int slab   = blockIdx.y;             // 0..5
    const int n_inst = gridDim.x;

    // ---- Repack: interleave head0/head1 weights into pairs ----
    if (tid < NP) {
        float w1 = p1[inst * NP + tid];
        float w2 = p2[inst * NP + tid];
        int d;
        if      (tid < 80)  { const int c = tid / 10; d = (tid - c * 10) * 8 + c; }        // l0wT
        else if (tid < 144) { const int i = tid - 80; d = 88 + (i / 8) * 10 + (i % 8); }   // l1w
        else if (tid < 152) { d = 88 + (tid - 144) * 10 + 9; w1 *= 0.5f; w2 *= 0.5f; }     // l2w
        else if (tid < 160) { d = 80 + (tid - 152); }                                      // l0b
        else if (tid < 168) { d = 88 + (tid - 160) * 10 + 8; }                             // l1b
        else                { d = 168; w1 *= 0.5f; w2 *= 0.5f; }                           // l2b
        swp[d] = pk(w1, w2);
    }

    const int   lvl     = fpn[inst];
    const float inv_soi = 1.0f / (64.0f * (float)(1 << lvl));
    const float lx0 = loc[2 * inst + 0];
    const float ly0 = loc[2 * inst + 1];
    const float lx1 = lx0 + off[2 * inst + 0] * 128.0f;
    const float ly1 = ly0 + off[2 * inst + 1] * 128.0f;
    const float* fb = feats + (size_t)imi[inst] * (8 * HW);
    const float dxs = -8.0f * inv_soi;
    __syncthreads();

    // ---------------- Phase 1: packed MLP, 2 px x 2 heads per iter ----------
    // slab s -> output rows [32s, 32s+32) -> input rows [16s-(s>0), 16s+16)
    const int ybase = 16 * slab - (slab ? 1 : 0);
    const int nrows = 16 + (slab ? 1 : 0);     // 16 or 17
    const int npx   = nrows * WW;

    #pragma unroll 1
    for (int p = 2 * tid; p < npx; p += 2 * NT) {
        const int rowl = p / WW;
        const int px   = p - rowl * WW;          // even
        const int y    = ybase + rowl;
        const int base = y * WW + px;

        // coordinate pairs {head0, head1}
        const float yc = (float)(y * 8 + 4);
        const float xc = (float)(px * 8 + 4);
        const u64 yp  = pk((ly0 - yc) * inv_soi, (ly1 - yc) * inv_soi);
        const u64 xpA = pk((lx0 - xc) * inv_soi, (lx1 - xc) * inv_soi);
        const u64 xpB = add2(xpA, dup(dxs));

        // features for the 2 pixels (8 x LDG.64)
        float2 f2[8];
        #pragma unroll
        for (int j = 0; j < 8; ++j)
            f2[j] = *reinterpret_cast<const float2*>(fb + j * HW + base);

        // layer-0 accumulators: bias pairs
        u64 a0[8], a1[8];
        {
            const ulonglong2* bp = reinterpret_cast<const ulonglong2*>(swp + 80);
            #pragma unroll
            for (int h = 0; h < 4; ++h) {
                const ulonglong2 b = bp[h];
                a0[2 * h] = b.x; a0[2 * h + 1] = b.y;
                a1[2 * h] = b.x; a1[2 * h + 1] = b.y;
            }
        }

        // layer 0, input-outer over transposed weights
        #define L0STEP(I, XA, XB)                                             \
        {                                                                     \
            const ulonglong2* Wp = reinterpret_cast<const ulonglong2*>(swp + (I) * 8); \
            const ulonglong2 wa = Wp[0], wb = Wp[1], wc = Wp[2], wd = Wp[3];  \
            a0[0] = ffma2(XA, wa.x, a0[0]);  a1[0] = ffma2(XB, wa.x, a1[0]);  \
            a0[1] = ffma2(XA, wa.y, a0[1]);  a1[1] = ffma2(XB, wa.y, a1[1]);  \
            a0[2] = ffma2(XA, wb.x, a0[2]);  a1[2] = ffma2(XB, wb.x, a1[2]);  \
            a0[3] = ffma2(XA, wb.y, a0[3]);  a1[3] = ffma2(XB, wb.y, a1[3]);  \
            a0[4] = ffma2(XA, wc.x, a0[4]);  a1[4] = ffma2(XB, wc.x, a1[4]);  \
            a0[5] = ffma2(XA, wc.y, a0[5]);  a1[5] = ffma2(XB, wc.y, a1[5]);  \
            a0[6] = ffma2(XA, wd.x, a0[6]);  a1[6] = ffma2(XB, wd.x, a1[6]);  \
            a0[7] = ffma2(XA, wd.y, a0[7]);  a1[7] = ffma2(XB, wd.y, a1[7]);  \
        }
        L0STEP(0, xpA, xpB)
        L0STEP(1, yp,  yp)
        #pragma unroll
        for (int j = 0; j < 8; ++j) {
            const u64 fd0 = dup(f2[j].x);
            const u64 fd1 = dup(f2[j].y);
            L0STEP(2 + j, fd0, fd1)
        }
        #undef L0STEP

        #pragma unroll
        for (int c = 0; c < 8; ++c) { a0[c] = relu2(a0[c]); a1[c] = relu2(a1[c]); }

        // layer 1 channel-outer ({bias,w2} packed), layer 2 streamed into o
        u64 o0 = swp[168], o1 = o0;
        #pragma unroll
        for (int c = 0; c < 8; ++c) {
            const ulonglong2* Wp = reinterpret_cast<const ulonglong2*>(swp + 88 + c * 10);
            const ulonglong2 wa = Wp[0], wb = Wp[1], wc = Wp[2], wd = Wp[3];
            const ulonglong2 bw = Wp[4];          // {bias, w2}
            u64 b0 = ffma2(a0[0], wa.x, bw.x);
            u64 b1 = ffma2(a1[0], wa.x, bw.x);
            b0 = ffma2(a0[1], wa.y, b0);  b1 = ffma2(a1[1], wa.y, b1);
            b0 = ffma2(a0[2], wb.x, b0);  b1 = ffma2(a1[2], wb.x, b1);
            b0 = ffma2(a0[3], wb.y, b0);  b1 = ffma2(a1[3], wb.y, b1);
            b0 = ffma2(a0[4], wc.x, b0);  b1 = ffma2(a1[4], wc.x, b1);
            b0 = ffma2(a0[5], wc.y, b0);  b1 = ffma2(a1[5], wc.y, b1);
            b0 = ffma2(a0[6], wd.x, b0);  b1 = ffma2(a1[6], wd.x, b1);
            b0 = ffma2(a0[7], wd.y, b0);  b1 = ffma2(a1[7], wd.y, b1);
            o0 = ffma2(relu2(b0), bw.y, o0);
            o1 = ffma2(relu2(b1), bw.y, o1);
        }

        sLp[rowl * WW + px]     = o0;    // packed {h0, h1} half-logits
        sLp[rowl * WW + px + 1] = o1;
    }
    __syncthreads();

    // ---------------- Phase 2: packed bilinear x2 + sigmoid ------------------
    // S_i = P[rA][i] + P[rB][i]  (rA==rB for odd rows -> S = 2P)
    //   col 4g: 0.25*(S_{cm1}+S_{c0})   4g+1: 0.5*S_{c0}
    //   4g+2:   0.25*(S_{c0}+S_{c1})    4g+3: 0.5*S_{c1}
    const u64 H = dup(0.5f);
    const u64 Q = dup(0.25f);
    float* ob0 = out + (size_t)inst * (192 * OW);
    float* ob1 = out + ((size_t)n_inst + inst) * (192 * OW);

    // 32 output rows x 80 quad-groups = 2560 items; 14 guarded iters
    #pragma unroll 1
    for (int it = 0; it < 14; ++it) {
        const int q = tid + it * NT;
        if (q >= 32 * 80) break;
        const int oyl = q / 80;                 // 0..31
        const int g   = q - oyl * 80;           // 0..79
        const int oy  = 32 * slab + oyl;

        const int r1  = oy >> 1;
        const int rA  = (oy & 1) ? r1 : ((r1 > 0) ? r1 - 1 : 0);
        const u64* RB = sLp + (r1 - ybase) * WW;
        const u64* RA = sLp + (rA - ybase) * WW;

        const int c0  = 2 * g;                  // even -> 16B aligned
        const int cm1 = (g > 0) ? c0 - 1 : c0;

        const ulonglong2 pb = *reinterpret_cast<const ulonglong2*>(RB + c0);
        const ulonglong2 pa = *reinterpret_cast<const ulonglong2*>(RA + c0);
        const u64 Sm = add2(RA[cm1], RB[cm1]);
        const u64 S0 = add2(pa.x, pb.x);
        const u64 S1 = add2(pa.y, pb.y);

        const u64 e0 = mul2(add2(Sm, S0), Q);
        const u64 e1 = mul2(S0, H);
        const u64 e2 = mul2(add2(S0, S1), Q);
        const u64 e3 = mul2(S1, H);

        float a0, b0, a1, b1, a2, b2, a3, b3;
        upk(e0, a0, b0); upk(e1, a1, b1); upk(e2, a2, b2); upk(e3, a3, b3);

        float4 v0, v1;
        v0.x = sig_h(a0); v0.y = sig_h(a1); v0.z = sig_h(a2); v0.w = sig_h(a3);
        v1.x = sig_h(b0); v1.y = sig_h(b1); v1.z = sig_h(b2); v1.w = sig_h(b3);

        const int o = oy * OW + 4 * g;
        *reinterpret_cast<float4*>(ob0 + o) = v0;
        *reinterpret_cast<float4*>(ob1 + o) = v1;
    }
}

extern "C" void kernel_launch(void* const* d_in, const int* in_sizes, int n_in,
                              void* d_out, int out_size)
{
    const float* feats = (const float*)d_in[0];
    const float* p1    = (const float*)d_in[1];
    const float* p2    = (const float*)d_in[2];
    const float* loc   = (const float*)d_in[3];
    const float* off   = (const float*)d_in[4];
    const int*   imi   = (const int*)  d_in[5];
    const int*   fpn   = (const int*)  d_in[6];
    float* out = (float*)d_out;

    const int n_inst = in_sizes[5];   // 200

    static bool attr_set = false;
    if (!attr_set) {
        cudaFuncSetAttribute(dmh_kernel,
                             cudaFuncAttributeMaxDynamicSharedMemorySize,
                             (int)SMEM_BYTES);
        attr_set = true;
    }

    dim3 grid(n_inst, 6);             // 1200 half-size blocks ~ 2 waves @4 CTA/SM
    dmh_kernel<<<grid, NT, SMEM_BYTES>>>(feats, p1, p2, loc, off, imi, fpn, out);
}